// round 10
// baseline (speedup 1.0000x reference)
#include <cuda_runtime.h>
#include <cstdint>

#ifndef USE_ORIGINAL_THREEFRY
#define USE_ORIGINAL_THREEFRY 0
#endif

namespace {

constexpr int F        = 256;   // N_FEATURES
constexpr int TM       = 64;    // rows per CTA
constexpr int TK       = 32;    // k-chunk staged in smem
constexpr int WPITCH   = 260;   // smem pitch (4k+g mod 32 -> conflict-free LDS.128)
constexpr int NTHREADS = 256;

constexpr int EMBT_ELEMS = F * TM;                 // 16384 floats
constexpr int WST_ELEMS  = TK * WPITCH;            // 8320 floats
constexpr int SMEM_BYTES = (EMBT_ELEMS + WST_ELEMS) * 4 + TM * 2 * 4;  // 99328 B

__device__ __forceinline__ uint32_t rotl32(uint32_t x, int d) {
    return __funnelshift_l(x, x, d);
}

// JAX threefry2x32: 20 rounds, key injections every 4 rounds.
__device__ __forceinline__ void tf2x32(uint32_t k0, uint32_t k1,
                                       uint32_t x0, uint32_t x1,
                                       uint32_t& o0, uint32_t& o1) {
    uint32_t k2 = k0 ^ k1 ^ 0x1BD11BDAu;
    x0 += k0; x1 += k1;
#define TF_R(r) { x0 += x1; x1 = rotl32(x1, (r)); x1 ^= x0; }
    TF_R(13) TF_R(15) TF_R(26) TF_R(6)   x0 += k1; x1 += k2 + 1u;
    TF_R(17) TF_R(29) TF_R(16) TF_R(24)  x0 += k2; x1 += k0 + 2u;
    TF_R(13) TF_R(15) TF_R(26) TF_R(6)   x0 += k0; x1 += k1 + 3u;
    TF_R(17) TF_R(29) TF_R(16) TF_R(24)  x0 += k1; x1 += k2 + 4u;
    TF_R(13) TF_R(15) TF_R(26) TF_R(6)   x0 += k2; x1 += k0 + 5u;
#undef TF_R
    o0 = x0; o1 = x1;
}

__device__ __forceinline__ float bits_to_uniform(uint32_t bits) {
    float f = __uint_as_float((bits >> 9) | 0x3f800000u);
    return (f - 1.0f) * 100.0f;
}

// ---- packed fp32x2 helpers (sm_100+): 2 FMAs per fma-pipe slot ----
__device__ __forceinline__ uint64_t f32x2_dup(float x) {
    uint64_t r;
    asm("mov.b64 %0, {%1, %1};" : "=l"(r) : "f"(x));
    return r;
}
__device__ __forceinline__ uint64_t f32x2_fma(uint64_t a, uint64_t b, uint64_t c) {
    uint64_t d;
    asm("fma.rn.f32x2 %0, %1, %2, %3;" : "=l"(d) : "l"(a), "l"(b), "l"(c));
    return d;
}
__device__ __forceinline__ float f32x2_lo(uint64_t v) {
    return __uint_as_float((uint32_t)v);
}
__device__ __forceinline__ float f32x2_hi(uint64_t v) {
    return __uint_as_float((uint32_t)(v >> 32));
}

__global__ void __launch_bounds__(NTHREADS, 2)
fused_embed_gemm(const float* __restrict__ x,
                 const float* __restrict__ W,
                 const float* __restrict__ bias,
                 float* __restrict__ out) {
    extern __shared__ float smem[];
    float* embT = smem;                         // [F][TM]
    float* WsT  = smem + EMBT_ELEMS;            // [TK][WPITCH]
    uint32_t* fk0 = reinterpret_cast<uint32_t*>(smem + EMBT_ELEMS + WST_ELEMS);
    uint32_t* fk1 = fk0 + TM;

    const int t       = threadIdx.x;
    const int rowBase = blockIdx.x * TM;

    // ---- Phase 0: fold_in per row: key' = threefry((0,42), (0, bitcast(x[row]))) ----
    if (t < TM) {
        uint32_t s = __float_as_uint(x[rowBase + t]);
        uint32_t a, b2;
        tf2x32(0u, 42u, 0u, s, a, b2);
        fk0[t] = a; fk1[t] = b2;
    }
    __syncthreads();

    // ---- Phase 1: generate embT[f][row] ----
#if !USE_ORIGINAL_THREEFRY
    // partitionable 32-bit draw: bits[f] = lane0 ^ lane1 of threefry(key, (0, f))
    #pragma unroll 2
    for (int rep = 0; rep < (TM * F) / NTHREADS; ++rep) {   // 64 reps
        int idx = t + rep * NTHREADS;
        int row = idx & (TM - 1);
        int f   = idx >> 6;
        uint32_t o0, o1;
        tf2x32(fk0[row], fk1[row], 0u, (uint32_t)f, o0, o1);
        embT[f * TM + row] = bits_to_uniform(o0 ^ o1);
    }
#else
    #pragma unroll 2
    for (int rep = 0; rep < (TM * 128) / NTHREADS; ++rep) {  // 32 reps
        int idx = t + rep * NTHREADS;
        int row = idx & (TM - 1);
        int i   = idx >> 6;
        uint32_t o0, o1;
        tf2x32(fk0[row], fk1[row], (uint32_t)i, (uint32_t)(i + 128u), o0, o1);
        embT[i * TM + row]         = bits_to_uniform(o0);
        embT[(i + 128) * TM + row] = bits_to_uniform(o1);
    }
#endif
    __syncthreads();

    // ---- Phase 2: out[rowBase..+64, :] = embT^T @ W^T + b, packed f32x2 FMA ----
    // 8 warps = 4 rowGroups x 2 colGroups. Warp tile: 16 rows x 128 cols.
    // Thread tile: 16 rows x 4 cols. acc2[rp][c] packs rows {2rp, 2rp+1}.
    const int warp   = t >> 5;
    const int lane   = t & 31;
    const int rowOff = (warp >> 1) * 16;          // 0,16,32,48
    const int cg     = (warp & 1) * 128;          // 0 or 128

    uint64_t acc2[8][4];
    #pragma unroll
    for (int rp = 0; rp < 8; ++rp)
        #pragma unroll
        for (int c = 0; c < 4; ++c) acc2[rp][c] = 0ull;

    for (int kb = 0; kb < F / TK; ++kb) {
        // Stage W[g][kb*TK + k] -> WsT[k][g] (transposed), 2048 float4 loads.
        #pragma unroll
        for (int j = 0; j < 8; ++j) {
            int lin = t + j * NTHREADS;        // 0..2047
            int g   = lin >> 3;                // 0..255
            int k4  = lin & 7;                 // 0..7
            float4 v = *reinterpret_cast<const float4*>(&W[g * F + kb * TK + k4 * 4]);
            WsT[(k4 * 4 + 0) * WPITCH + g] = v.x;
            WsT[(k4 * 4 + 1) * WPITCH + g] = v.y;
            WsT[(k4 * 4 + 2) * WPITCH + g] = v.z;
            WsT[(k4 * 4 + 3) * WPITCH + g] = v.w;
        }
        __syncthreads();

        const float* embBase = &embT[(kb * TK) * TM + rowOff];
        const float* wBase   = &WsT[cg + lane * 4];

        #pragma unroll 2
        for (int k = 0; k < TK; ++k) {
            // a: 16 rows = 4x LDS.128 broadcast; pairs come free as f32x2
            uint64_t ap[8];
            #pragma unroll
            for (int q = 0; q < 4; ++q) {
                double2 aq = *reinterpret_cast<const double2*>(embBase + k * TM + q * 4);
                ap[2 * q + 0] = __double_as_longlong(aq.x);   // rows 4q+0,4q+1
                ap[2 * q + 1] = __double_as_longlong(aq.y);   // rows 4q+2,4q+3
            }

            // b: 4 cols, duplicated into both halves
            float4 bv = *reinterpret_cast<const float4*>(wBase + k * WPITCH);
            uint64_t bd[4];
            bd[0] = f32x2_dup(bv.x); bd[1] = f32x2_dup(bv.y);
            bd[2] = f32x2_dup(bv.z); bd[3] = f32x2_dup(bv.w);

            #pragma unroll
            for (int rp = 0; rp < 8; ++rp)
                #pragma unroll
                for (int c = 0; c < 4; ++c)
                    acc2[rp][c] = f32x2_fma(ap[rp], bd[c], acc2[rp][c]);
        }
        __syncthreads();
    }

    // ---- Epilogue: add bias, store 16 rows x 4 cols ----
    const float4 bv = *reinterpret_cast<const float4*>(&bias[cg + lane * 4]);
    #pragma unroll
    for (int rp = 0; rp < 8; ++rp) {
        const size_t r0 = (size_t)(rowBase + rowOff + 2 * rp);
        float4 lo, hi;
        lo.x = f32x2_lo(acc2[rp][0]) + bv.x;  hi.x = f32x2_hi(acc2[rp][0]) + bv.x;
        lo.y = f32x2_lo(acc2[rp][1]) + bv.y;  hi.y = f32x2_hi(acc2[rp][1]) + bv.y;
        lo.z = f32x2_lo(acc2[rp][2]) + bv.z;  hi.z = f32x2_hi(acc2[rp][2]) + bv.z;
        lo.w = f32x2_lo(acc2[rp][3]) + bv.w;  hi.w = f32x2_hi(acc2[rp][3]) + bv.w;
        *reinterpret_cast<float4*>(&out[r0 * F + cg + lane * 4])       = lo;
        *reinterpret_cast<float4*>(&out[(r0 + 1) * F + cg + lane * 4]) = hi;
    }
}

} // anonymous namespace

extern "C" void kernel_launch(void* const* d_in, const int* in_sizes, int n_in,
                              void* d_out, int out_size) {
    const float* x    = (const float*)d_in[0];   // [131072] fp32 (256x512)
    const float* W    = (const float*)d_in[1];   // [256,256] fp32 row-major W[g][f]
    const float* bias = (const float*)d_in[2];   // [256]
    float* out        = (float*)d_out;           // [131072, 256]

    const int nrows = in_sizes[0];               // 131072
    const int grid  = nrows / TM;                // 2048

    cudaFuncSetAttribute(fused_embed_gemm,
                         cudaFuncAttributeMaxDynamicSharedMemorySize, SMEM_BYTES);
    fused_embed_gemm<<<grid, NTHREADS, SMEM_BYTES>>>(x, W, bias, out);
}